// round 4
// baseline (speedup 1.0000x reference)
#include <cuda_runtime.h>
#include <cstdint>

// Transformer_66529043415377: flow-driven bilinear warp, reference quirks:
// y clamped to [0, C-1]=[0,2], x to [0, H-1]=[0,511], raw [N,3] interleaved out.
//
// Exact-zero structure: with the reference's rounding order, a pixel is
// nonzero ONLY when clamped y0 != y1, i.e. floor(y) in {0,1}, i.e. y in [0,2).
// (y0<=-1 or y0>=2 -> both clamp to the same row, wb=-wa, wd=-wc exactly,
// left-assoc sum cancels to +0.0.) So the active test is just two compares.
//
// Layout: 8 pixels/thread. Fast path: 2x LDG.128 (dy) + 6x STG.128 zeros.
// Slow path (rare, low-h rows only): dx load + bit-exact bilinear gather.

namespace {
constexpr int B  = 16;
constexpr int H  = 512;
constexpr int W  = 512;
constexpr int HW = H * W;           // 262144
constexpr int N  = B * HW;          // 4194304 pixels
constexpr int PIX = 8;
constexpr int THREADS = 128;
}

__global__ __launch_bounds__(THREADS)
void transformer_warp_kernel(const float* __restrict__ flow,
                             const float* __restrict__ pqf,
                             float* __restrict__ out)
{
    const int t = blockIdx.x * blockDim.x + threadIdx.x;
    const int i = t * PIX;                      // base pixel index

    const int b   = i >> 18;                    // / HW
    const int rem = i & (HW - 1);
    const int h   = rem >> 9;                   // / W
    const int w   = rem & (W - 1);              // w..w+7 stay in-row (512%8==0)

    const float* fbase = flow + (size_t)b * 2 * HW + rem;
    // front-batched dy loads (MLP=2); rem multiple of 8 -> 16B aligned
    const float4 dyA = *reinterpret_cast<const float4*>(fbase + HW);
    const float4 dyB = *reinterpret_cast<const float4*>(fbase + HW + 4);

    const float dys[8] = {dyA.x, dyA.y, dyA.z, dyA.w,
                          dyB.x, dyB.y, dyB.z, dyB.w};
    const float yf = (float)h;

    float yv[8];
    bool  act[8];
    bool  any = false;

#pragma unroll
    for (int j = 0; j < 8; ++j) {
        // dy*64 exact (power-of-two scale) -> rounding matches reference
        const float y = __fadd_rn(yf, __fmul_rn(dys[j], 64.0f));
        yv[j]  = y;
        act[j] = (y >= 0.0f) && (y < 2.0f);     // <=> clamped y0 != y1
        any |= act[j];
    }

    // out + i*3: i multiple of 8 -> 96B offset, 16B aligned
    float4* o = reinterpret_cast<float4*>(out + (size_t)i * 3);

    if (!any) {
        const float4 z = make_float4(0.0f, 0.0f, 0.0f, 0.0f);
        o[0] = z; o[1] = z; o[2] = z; o[3] = z; o[4] = z; o[5] = z;
        return;
    }

    // Rare path: at least one active pixel among the 8.
    const float4 dxA = *reinterpret_cast<const float4*>(fbase);
    const float4 dxB = *reinterpret_cast<const float4*>(fbase + 4);
    const float dxs[8] = {dxA.x, dxA.y, dxA.z, dxA.w,
                          dxB.x, dxB.y, dxB.z, dxB.w};

    const int baseb = b << 9;                   // b * dim1 (=W=512)

#pragma unroll
    for (int g = 0; g < 2; ++g) {
        float res[12];
#pragma unroll
        for (int jj = 0; jj < 4; ++jj) {
            const int j = g * 4 + jj;
            if (!act[j]) {
                res[jj * 3 + 0] = 0.0f;
                res[jj * 3 + 1] = 0.0f;
                res[jj * 3 + 2] = 0.0f;
                continue;
            }

            const float y = yv[j];
            const float x = __fadd_rn((float)(w + j), __fmul_rn(dxs[j], 64.0f));

            float x0f = floorf(x);
            float x1f = __fadd_rn(x0f, 1.0f);
            x0f = fminf(fmaxf(x0f, 0.0f), 511.0f);   // max_x = H-1 = 511
            x1f = fminf(fmaxf(x1f, 0.0f), 511.0f);

            // active => y in [0,2): floor(y) in {0,1}; clamps are no-ops but
            // values equal the reference's clamped y0,y1 exactly.
            const float y0f = floorf(y);
            const float y1f = __fadd_rn(y0f, 1.0f);

            const int ix0 = (int)x0f;
            const int ix1 = (int)x1f;
            const int iy0 = (int)y0f;
            const int iy1 = (int)y1f;

            const int idx_a = baseb + iy0 * HW + ix0;
            const int idx_b = baseb + iy1 * HW + ix0;
            const int idx_c = baseb + iy0 * HW + ix1;
            const int idx_d = baseb + iy1 * HW + ix1;

            const float wxa = __fsub_rn(x1f, x);
            const float wxc = __fsub_rn(x, x0f);
            const float wya = __fsub_rn(y1f, y);
            const float wyb = __fsub_rn(y, y0f);
            const float wa = __fmul_rn(wxa, wya);
            const float wb = __fmul_rn(wxa, wyb);
            const float wc = __fmul_rn(wxc, wya);
            const float wd = __fmul_rn(wxc, wyb);

            const float* pa = pqf + (size_t)idx_a * 3;
            const float* pb = pqf + (size_t)idx_b * 3;
            const float* pc = pqf + (size_t)idx_c * 3;
            const float* pd = pqf + (size_t)idx_d * 3;

#pragma unroll
            for (int c = 0; c < 3; ++c) {
                // exact reference order: ((wa*A + wb*B) + wc*C) + wd*D
                const float pA = __fmul_rn(wa, __ldg(pa + c));
                const float pB = __fmul_rn(wb, __ldg(pb + c));
                const float pC = __fmul_rn(wc, __ldg(pc + c));
                const float pD = __fmul_rn(wd, __ldg(pd + c));
                res[jj * 3 + c] = __fadd_rn(__fadd_rn(__fadd_rn(pA, pB), pC), pD);
            }
        }
        o[g * 3 + 0] = make_float4(res[0], res[1], res[2],  res[3]);
        o[g * 3 + 1] = make_float4(res[4], res[5], res[6],  res[7]);
        o[g * 3 + 2] = make_float4(res[8], res[9], res[10], res[11]);
    }
}

extern "C" void kernel_launch(void* const* d_in, const int* in_sizes, int n_in,
                              void* d_out, int out_size)
{
    const float* flow = (const float*)d_in[0];
    const float* pqf  = (const float*)d_in[1];
    float* out        = (float*)d_out;

    const int blocks = N / (PIX * THREADS);     // 4096
    transformer_warp_kernel<<<blocks, THREADS>>>(flow, pqf, out);
}

// round 6
// speedup vs baseline: 1.1508x; 1.1508x over previous
#include <cuda_runtime.h>
#include <cstdint>

// Transformer_66529043415377: flow-driven bilinear warp, reference quirks:
// y clamped to [0, C-1]=[0,2], x to [0, H-1]=[0,511], raw [N,3] interleaved out.
//
// Exact-zero structure: with the reference's rounding order, a pixel is
// nonzero ONLY when clamped y0 != y1, i.e. y in [0,2). Otherwise both rows
// clamp equal, wb=-wa, wd=-wc exactly, and the left-assoc sum cancels to +0.0.
//
// NOTE on FFMA: dy*64 and dx*64 are EXACT (power-of-two scale), so
// fmaf(dy, 64, yf) rounds the exact result once == fadd(yf, fmul(dy,64)).
// Bit-identical to the reference, one instruction instead of two.
//
// Shape: 4 px/thread, 128-thread CTAs, 8192 blocks (32K warps chip-wide —
// the latency-hiding sweet spot found in R3/R4).

namespace {
constexpr int B  = 16;
constexpr int H  = 512;
constexpr int W  = 512;
constexpr int HW = H * W;           // 262144
constexpr int N  = B * HW;          // 4194304 pixels
constexpr int PIX = 4;
constexpr int THREADS = 128;
}

__global__ __launch_bounds__(THREADS)
void transformer_warp_kernel(const float* __restrict__ flow,
                             const float* __restrict__ pqf,
                             float* __restrict__ out)
{
    const int t = blockIdx.x * blockDim.x + threadIdx.x;
    const int i = t * PIX;                      // base pixel index

    const int b   = i >> 18;                    // / HW
    const int rem = i & (HW - 1);
    const int h   = rem >> 9;                   // / W
    const int w   = rem & (W - 1);

    const float* fbase = flow + (size_t)b * 2 * HW + rem;
    const float4 dy4 = *reinterpret_cast<const float4*>(fbase + HW);

    const float yf = (float)h;

    // fmaf is bit-exact here (dy*64 exact) — see note above.
    const float y0 = __fmaf_rn(dy4.x, 64.0f, yf);
    const float y1 = __fmaf_rn(dy4.y, 64.0f, yf);
    const float y2 = __fmaf_rn(dy4.z, 64.0f, yf);
    const float y3 = __fmaf_rn(dy4.w, 64.0f, yf);

    const bool a0 = (y0 >= 0.0f) && (y0 < 2.0f);
    const bool a1 = (y1 >= 0.0f) && (y1 < 2.0f);
    const bool a2 = (y2 >= 0.0f) && (y2 < 2.0f);
    const bool a3 = (y3 >= 0.0f) && (y3 < 2.0f);

    float4* o = reinterpret_cast<float4*>(out + (size_t)i * 3);

    if (!(a0 | a1 | a2 | a3)) {
        // All four pixels cancel exactly to +0.0 in the reference order.
        const float4 z = make_float4(0.0f, 0.0f, 0.0f, 0.0f);
        o[0] = z; o[1] = z; o[2] = z;
        return;
    }

    // Rare path: at least one active pixel among the 4.
    const float4 dx4 = *reinterpret_cast<const float4*>(fbase);
    const float dxs[4] = {dx4.x, dx4.y, dx4.z, dx4.w};
    const float yv[4]  = {y0, y1, y2, y3};
    const bool  act[4] = {a0, a1, a2, a3};

    const int baseb = b << 9;                   // b * dim1 (=W=512)
    float res[12];

#pragma unroll
    for (int j = 0; j < 4; ++j) {
        if (!act[j]) {
            res[j * 3 + 0] = 0.0f;
            res[j * 3 + 1] = 0.0f;
            res[j * 3 + 2] = 0.0f;
            continue;
        }

        const float y = yv[j];
        const float x = __fmaf_rn(dxs[j], 64.0f, (float)(w + j)); // bit-exact

        float x0f = floorf(x);
        float x1f = __fadd_rn(x0f, 1.0f);
        x0f = fminf(fmaxf(x0f, 0.0f), 511.0f);   // max_x = H-1 = 511
        x1f = fminf(fmaxf(x1f, 0.0f), 511.0f);

        // active => y in [0,2): floor(y) in {0,1}; equals reference's
        // clamped y0,y1 exactly (clamps are no-ops on this range).
        const float y0f = floorf(y);
        const float y1f = __fadd_rn(y0f, 1.0f);

        const int ix0 = (int)x0f;
        const int ix1 = (int)x1f;
        const int iy0 = (int)y0f;
        const int iy1 = (int)y1f;

        const int idx_a = baseb + iy0 * HW + ix0;
        const int idx_b = baseb + iy1 * HW + ix0;
        const int idx_c = baseb + iy0 * HW + ix1;
        const int idx_d = baseb + iy1 * HW + ix1;

        // single-rounded weight products (no contractible fma pattern)
        const float wxa = __fsub_rn(x1f, x);
        const float wxc = __fsub_rn(x, x0f);
        const float wya = __fsub_rn(y1f, y);
        const float wyb = __fsub_rn(y, y0f);
        const float wa = __fmul_rn(wxa, wya);
        const float wb = __fmul_rn(wxa, wyb);
        const float wc = __fmul_rn(wxc, wya);
        const float wd = __fmul_rn(wxc, wyb);

        const float* pa = pqf + (size_t)idx_a * 3;
        const float* pb = pqf + (size_t)idx_b * 3;
        const float* pc = pqf + (size_t)idx_c * 3;
        const float* pd = pqf + (size_t)idx_d * 3;

#pragma unroll
        for (int c = 0; c < 3; ++c) {
            // exact reference order: ((wa*A + wb*B) + wc*C) + wd*D,
            // each product individually rounded, no contraction
            const float pA = __fmul_rn(wa, __ldg(pa + c));
            const float pB = __fmul_rn(wb, __ldg(pb + c));
            const float pC = __fmul_rn(wc, __ldg(pc + c));
            const float pD = __fmul_rn(wd, __ldg(pd + c));
            res[j * 3 + c] = __fadd_rn(__fadd_rn(__fadd_rn(pA, pB), pC), pD);
        }
    }

    o[0] = make_float4(res[0], res[1], res[2],  res[3]);
    o[1] = make_float4(res[4], res[5], res[6],  res[7]);
    o[2] = make_float4(res[8], res[9], res[10], res[11]);
}

extern "C" void kernel_launch(void* const* d_in, const int* in_sizes, int n_in,
                              void* d_out, int out_size)
{
    const float* flow = (const float*)d_in[0];
    const float* pqf  = (const float*)d_in[1];
    float* out        = (float*)d_out;

    const int blocks = N / (PIX * THREADS);     // 8192
    transformer_warp_kernel<<<blocks, THREADS>>>(flow, pqf, out);
}